// round 1
// baseline (speedup 1.0000x reference)
#include <cuda_runtime.h>
#include <cstdint>

// Problem constants (fixed by setup_inputs)
#define BB 4
#define TT 2048
#define DD 512
#define HH 8
#define DK 64
#define BHN (BB*HH)          // 32
#define MROWS (BB*TT)        // 8192

// ---------------- scratch (static __device__ — no allocations) ----------------
__device__ unsigned long long g_qb[BHN*TT];        // q spike bits, [b*8+h][t], 64 bits = dk
__device__ unsigned long long g_kb[BHN*TT];
__device__ unsigned long long g_vb[BHN*TT];
__device__ unsigned long long g_vT[BHN*DK*(TT/64)];// v column bitmasks over k: [bh][d][w]
__device__ unsigned char      g_xs[BB*TT*DD];      // scrambled X bytes (0/1)

// ---------------- f32x2 helpers (per-lane IEEE fp32 FMA, 2x throughput) -------
__device__ __forceinline__ unsigned long long pk2(float lo, float hi) {
    unsigned long long r;
    asm("mov.b64 %0, {%1,%2};" : "=l"(r) : "f"(lo), "f"(hi));
    return r;
}
__device__ __forceinline__ void unpk2(unsigned long long v, float& lo, float& hi) {
    asm("mov.b64 {%0,%1}, %2;" : "=f"(lo), "=f"(hi) : "l"(v));
}
__device__ __forceinline__ void fma2(unsigned long long& d, unsigned long long a,
                                     unsigned long long b) {
    asm("fma.rn.f32x2 %0, %1, %2, %0;" : "+l"(d) : "l"(a), "l"(b));
}

// ---------------- projection GEMM + spike + bitpack ---------------------------
// C = A[M,K] @ W[K,512] + bias ; spike >= 1.0 ; pack 64 n-bits/head into uint64
// BM=128, BN=128, KT=16, 256 threads, 8x8 per thread via 4 f32x2 pairs.
template <int WHICH, bool VEC>
__global__ __launch_bounds__(256) void proj_pack_kernel(
    const float* __restrict__ A, const float* __restrict__ W,
    const float* __restrict__ bias, int K)
{
    __shared__ float Ash[16][128];
    __shared__ float Wsh[16][128];
    __shared__ unsigned char sb[128][16];

    const int tid = threadIdx.x;
    const int tx = tid & 15, ty = tid >> 4;
    const int m0 = blockIdx.y * 128, n0 = blockIdx.x * 128;

    unsigned long long acc[8][4];
#pragma unroll
    for (int i = 0; i < 8; i++)
#pragma unroll
        for (int p = 0; p < 4; p++) acc[i][p] = 0ull;

    const int amm = tid >> 1, akoff = (tid & 1) * 8;
    const int wkk = tid >> 4, wnoff = (tid & 15) * 8;

    for (int k0 = 0; k0 < K; k0 += 16) {
        // ---- A tile (transposed to [k][m]) ----
        if (VEC) {
            const float4* ap = (const float4*)(A + (size_t)(m0 + amm) * K + k0 + akoff);
            float4 v0 = ap[0], v1 = ap[1];
            Ash[akoff + 0][amm] = v0.x; Ash[akoff + 1][amm] = v0.y;
            Ash[akoff + 2][amm] = v0.z; Ash[akoff + 3][amm] = v0.w;
            Ash[akoff + 4][amm] = v1.x; Ash[akoff + 5][amm] = v1.y;
            Ash[akoff + 6][amm] = v1.z; Ash[akoff + 7][amm] = v1.w;
        } else {
#pragma unroll
            for (int j = 0; j < 8; j++) {
                int kk = akoff + j;
                Ash[kk][amm] = (k0 + kk < K) ? A[(size_t)(m0 + amm) * K + k0 + kk] : 0.f;
            }
        }
        // ---- W tile [k][n] ----
        if (k0 + wkk < K) {
            const float4* wp = (const float4*)(W + (size_t)(k0 + wkk) * DD + n0 + wnoff);
            float4 v0 = wp[0], v1 = wp[1];
            Wsh[wkk][wnoff + 0] = v0.x; Wsh[wkk][wnoff + 1] = v0.y;
            Wsh[wkk][wnoff + 2] = v0.z; Wsh[wkk][wnoff + 3] = v0.w;
            Wsh[wkk][wnoff + 4] = v1.x; Wsh[wkk][wnoff + 5] = v1.y;
            Wsh[wkk][wnoff + 6] = v1.z; Wsh[wkk][wnoff + 7] = v1.w;
        } else {
#pragma unroll
            for (int j = 0; j < 8; j++) Wsh[wkk][wnoff + j] = 0.f;
        }
        __syncthreads();
#pragma unroll
        for (int kk = 0; kk < 16; ++kk) {
            float a[8];
#pragma unroll
            for (int i = 0; i < 8; i++) a[i] = Ash[kk][ty + 16 * i];
            unsigned long long wv[4];
#pragma unroll
            for (int p = 0; p < 4; p++)
                wv[p] = *(const unsigned long long*)&Wsh[kk][tx * 8 + 2 * p];
#pragma unroll
            for (int i = 0; i < 8; i++) {
                unsigned long long av = pk2(a[i], a[i]);
#pragma unroll
                for (int p = 0; p < 4; p++) fma2(acc[i][p], av, wv[p]);
            }
        }
        __syncthreads();
    }

    // ---- spike + byte stage ----
    float bl[8];
#pragma unroll
    for (int j = 0; j < 8; j++) bl[j] = bias[n0 + tx * 8 + j];
#pragma unroll
    for (int i = 0; i < 8; i++) {
        unsigned byt = 0;
#pragma unroll
        for (int p = 0; p < 4; p++) {
            float lo, hi;
            unpk2(acc[i][p], lo, hi);
            if (lo + bl[2 * p]     >= 1.0f) byt |= 1u << (2 * p);
            if (hi + bl[2 * p + 1] >= 1.0f) byt |= 1u << (2 * p + 1);
        }
        sb[ty + 16 * i][tx] = (unsigned char)byt;
    }
    __syncthreads();
    // ---- pack 8 bytes -> uint64 and store (one head per 64 n) ----
    {
        int row = tid >> 1, hf = tid & 1;
        unsigned long long wdat = *(const unsigned long long*)&sb[row][hf * 8];
        int m = m0 + row;
        int b = m >> 11, t = m & 2047;
        int head = (n0 >> 6) + hf;
        unsigned long long* dst = (WHICH == 0) ? g_qb : (WHICH == 1) ? g_kb : g_vb;
        dst[(size_t)((b << 3) + head) * TT + t] = wdat;
    }
}

// ---------------- v bit transpose: vT[bh][d][w] = bits over 64 k ---------------
__global__ void vtrans_kernel()
{
    int bx = blockIdx.x;       // 32*32
    int bh = bx >> 5, w = bx & 31;
    int tid = threadIdx.x;     // 64
    int lane = tid & 31, warp = tid >> 5;
    __shared__ unsigned sh[64][2];
    unsigned long long r = g_vb[(size_t)bh * TT + w * 64 + tid];
#pragma unroll 8
    for (int d = 0; d < 64; d++) {
        unsigned b = __ballot_sync(0xffffffffu, (unsigned)((r >> d) & 1ull));
        if (lane == 0) sh[d][warp] = b;
    }
    __syncthreads();
    g_vT[(size_t)(bh * 64 + tid) * 32 + w] =
        (unsigned long long)sh[tid][0] | ((unsigned long long)sh[tid][1] << 32);
}

// ---------------- attention: popcount QK + bit-plane PV + spike + scatter -----
// block: 128 threads = 4 warps. d = tid&63, t-half = tid>>6, k-half = warp&1.
__global__ __launch_bounds__(128) void attn_kernel(const float* __restrict__ scale_p)
{
    const int tid  = threadIdx.x;
    const int lane = tid & 31;
    const int warp = tid >> 5;
    const int half = tid >> 6;      // which 32 t-rows this thread handles
    const int khalf = warp & 1;     // which 32 k-cols this warp handles in plane-gen
    const int d = tid & 63;

    int bx = blockIdx.x;            // 1024
    int bh = bx & 31;
    int tq = 31 - (bx >> 5);        // big tiles scheduled first

    __shared__ unsigned long long qsh[64], ksh[64];
    __shared__ unsigned planes[64][7][2];
    __shared__ int accs[64][64];

    const float scale = *scale_p;
    const size_t base = (size_t)bh * TT;

    if (tid < 64) qsh[tid] = g_qb[base + tq * 64 + tid];
    for (int t0 = 0; t0 < 32; ++t0) accs[half * 32 + t0][d] = 0;
    __syncthreads();

    for (int w = 0; w <= tq; ++w) {
        if (tid < 64) ksh[tid] = g_kb[base + w * 64 + tid];
        unsigned long long vm = g_vT[(size_t)(bh * 64 + d) * 32 + w];
        __syncthreads();
        // ---- plane generation: cnt bit-planes over this k-tile ----
        {
            unsigned long long kr = ksh[khalf * 32 + lane];
            const bool diag = (w == tq);
            const int kloc = khalf * 32 + lane;
            for (int ttl = 0; ttl < 32; ++ttl) {
                int t = half * 32 + ttl;
                int cnt = __popcll(qsh[t] & kr);
                if (diag && kloc > t) cnt = 0;      // causal: keep k <= t
                unsigned mine = 0;
#pragma unroll
                for (int j = 0; j < 7; ++j) {
                    unsigned b = __ballot_sync(0xffffffffu, (cnt >> j) & 1);
                    if (lane == j) mine = b;
                }
                if (lane < 7) planes[t][lane][khalf] = mine;
            }
        }
        __syncthreads();
        // ---- accumulate S[t][d] += sum_j popc(plane_j & v_col) << j ----
        {
            unsigned vlo = (unsigned)vm, vhi = (unsigned)(vm >> 32);
            for (int ttl = 0; ttl < 32; ++ttl) {
                int t = half * 32 + ttl;
                int s = 0;
#pragma unroll
                for (int j = 0; j < 7; ++j)
                    s += (__popc(planes[t][j][0] & vlo) +
                          __popc(planes[t][j][1] & vhi)) << j;
                accs[t][d] += s;
            }
        }
        __syncthreads();
    }

    // ---- spike + scatter into scrambled layout: p = h*2^17 + d*2^11 + t ----
    {
        size_t b = (size_t)(bh >> 3);
        size_t h = (size_t)(bh & 7);
        size_t off = (b << 20) + (h << 17) + ((size_t)d << 11)
                   + (size_t)tq * 64 + (size_t)half * 32;
        for (int t0 = 0; t0 < 32; t0 += 8) {
            unsigned long long wv = 0;
#pragma unroll
            for (int j = 0; j < 8; ++j) {
                float v = (float)accs[half * 32 + t0 + j][d] * scale;
                if (v >= 1.0f) wv |= 1ull << (8 * j);
            }
            *(unsigned long long*)(g_xs + off + t0) = wv;
        }
    }
}

// ---------------- output projection: spike(Xscr @ Wo + bo) -> fp32 ------------
__global__ __launch_bounds__(256) void out_proj_kernel(
    const float* __restrict__ W, const float* __restrict__ bias,
    float* __restrict__ out)
{
    __shared__ float Ash[16][128];
    __shared__ float Wsh[16][128];

    const int tid = threadIdx.x;
    const int tx = tid & 15, ty = tid >> 4;
    const int m0 = blockIdx.y * 128, n0 = blockIdx.x * 128;

    unsigned long long acc[8][4];
#pragma unroll
    for (int i = 0; i < 8; i++)
#pragma unroll
        for (int p = 0; p < 4; p++) acc[i][p] = 0ull;

    const int amm = tid >> 1, akoff = (tid & 1) * 8;
    const int wkk = tid >> 4, wnoff = (tid & 15) * 8;

    for (int k0 = 0; k0 < DD; k0 += 16) {
        {
            unsigned long long u =
                *(const unsigned long long*)(g_xs + (size_t)(m0 + amm) * DD + k0 + akoff);
#pragma unroll
            for (int j = 0; j < 8; j++)
                Ash[akoff + j][amm] = (float)(int)((u >> (8 * j)) & 1ull);
        }
        {
            const float4* wp = (const float4*)(W + (size_t)(k0 + wkk) * DD + n0 + wnoff);
            float4 v0 = wp[0], v1 = wp[1];
            Wsh[wkk][wnoff + 0] = v0.x; Wsh[wkk][wnoff + 1] = v0.y;
            Wsh[wkk][wnoff + 2] = v0.z; Wsh[wkk][wnoff + 3] = v0.w;
            Wsh[wkk][wnoff + 4] = v1.x; Wsh[wkk][wnoff + 5] = v1.y;
            Wsh[wkk][wnoff + 6] = v1.z; Wsh[wkk][wnoff + 7] = v1.w;
        }
        __syncthreads();
#pragma unroll
        for (int kk = 0; kk < 16; ++kk) {
            float a[8];
#pragma unroll
            for (int i = 0; i < 8; i++) a[i] = Ash[kk][ty + 16 * i];
            unsigned long long wv[4];
#pragma unroll
            for (int p = 0; p < 4; p++)
                wv[p] = *(const unsigned long long*)&Wsh[kk][tx * 8 + 2 * p];
#pragma unroll
            for (int i = 0; i < 8; i++) {
                unsigned long long av = pk2(a[i], a[i]);
#pragma unroll
                for (int p = 0; p < 4; p++) fma2(acc[i][p], av, wv[p]);
            }
        }
        __syncthreads();
    }

    float bl[8];
#pragma unroll
    for (int j = 0; j < 8; j++) bl[j] = bias[n0 + tx * 8 + j];
#pragma unroll
    for (int i = 0; i < 8; i++) {
        int m = m0 + ty + 16 * i;
#pragma unroll
        for (int p = 0; p < 4; p++) {
            float lo, hi;
            unpk2(acc[i][p], lo, hi);
            float2 r;
            r.x = (lo + bl[2 * p]     >= 1.0f) ? 1.0f : 0.0f;
            r.y = (hi + bl[2 * p + 1] >= 1.0f) ? 1.0f : 0.0f;
            *(float2*)&out[(size_t)m * DD + n0 + tx * 8 + 2 * p] = r;
        }
    }
}

// ---------------- launch ------------------------------------------------------
extern "C" void kernel_launch(void* const* d_in, const int* in_sizes, int n_in,
                              void* d_out, int out_size)
{
    const float* query = (const float*)d_in[0];
    const float* key   = (const float*)d_in[1];
    const float* value = (const float*)d_in[2];
    const float* scale = (const float*)d_in[3];
    const float* Wq = (const float*)d_in[4];  const float* bq = (const float*)d_in[5];
    const float* Wk = (const float*)d_in[6];  const float* bk = (const float*)d_in[7];
    const float* Wv = (const float*)d_in[8];  const float* bv = (const float*)d_in[9];
    const float* Wo = (const float*)d_in[10]; const float* bo = (const float*)d_in[11];
    float* out = (float*)d_out;

    const int DIN = in_sizes[0] / MROWS;   // 100

    dim3 grid(4, 64), blk(256);
    proj_pack_kernel<0, false><<<grid, blk>>>(query, Wq, bq, DIN);
    proj_pack_kernel<1, true ><<<grid, blk>>>(key,   Wk, bk, DD);
    proj_pack_kernel<2, true ><<<grid, blk>>>(value, Wv, bv, DD);
    vtrans_kernel<<<BHN * (TT / 64), 64>>>();
    attn_kernel<<<BHN * (TT / 64), 128>>>(scale);
    out_proj_kernel<<<grid, blk>>>(Wo, bo, out);
}

// round 3
// speedup vs baseline: 2.1070x; 2.1070x over previous
#include <cuda_runtime.h>
#include <cstdint>

#define BB 4
#define TT 2048
#define DD 512
#define HH 8
#define DK 64
#define BHN (BB*HH)          // 32
#define MROWS (BB*TT)        // 8192

// ---------------- scratch ----------------
__device__ unsigned long long g_qb[BHN*TT];
__device__ unsigned long long g_kb[BHN*TT];
__device__ unsigned long long g_vb[BHN*TT];
__device__ unsigned long long g_vT[BHN*DK*(TT/64)];   // [bh][d][w] bits over 64 k
__device__ unsigned char      g_xs[BB*TT*DD];         // scrambled X bytes

// ---------------- f32x2 helpers ----------------
__device__ __forceinline__ unsigned long long pk2(float lo, float hi) {
    unsigned long long r;
    asm("mov.b64 %0, {%1,%2};" : "=l"(r) : "f"(lo), "f"(hi));
    return r;
}
__device__ __forceinline__ void unpk2(unsigned long long v, float& lo, float& hi) {
    asm("mov.b64 {%0,%1}, %2;" : "=f"(lo), "=f"(hi) : "l"(v));
}
__device__ __forceinline__ void fma2(unsigned long long& d, unsigned long long a,
                                     unsigned long long b) {
    asm("fma.rn.f32x2 %0, %1, %2, %0;" : "+l"(d) : "l"(a), "l"(b));
}
__device__ __forceinline__ unsigned expand4(unsigned x) {   // 4 bits -> 4 bytes
    return (x * 0x00204081u) & 0x01010101u;
}
__device__ __forceinline__ void mma_s8(int* c, unsigned a0, unsigned a1, unsigned a2,
                                       unsigned a3, unsigned b0, unsigned b1) {
    asm volatile(
        "mma.sync.aligned.m16n8k32.row.col.s32.s8.s8.s32 "
        "{%0,%1,%2,%3}, {%4,%5,%6,%7}, {%8,%9}, {%0,%1,%2,%3};"
        : "+r"(c[0]), "+r"(c[1]), "+r"(c[2]), "+r"(c[3])
        : "r"(a0), "r"(a1), "r"(a2), "r"(a3), "r"(b0), "r"(b1));
}

// =====================================================================
// Fused q/k/v projection + spike + bitpack.
// 768 blocks: [0,512) = k/v interleaved (heavy, scheduled first),
//             [512,768) = q (K=100, light, fills the tail wave).
// Thread map: tx=tid&15 (n), ty=tid>>4 (m); outputs n = n0+tx*2+32p+{0,1},
// m = m0+ty*2+32i+{0,1}  -> all smem reads are contiguous conflict-free LDS.64.
// =====================================================================
__global__ __launch_bounds__(256, 2) void qkv_proj_kernel(
    const float* __restrict__ Aq, const float* __restrict__ Ak,
    const float* __restrict__ Av,
    const float* __restrict__ Wq, const float* __restrict__ Wk,
    const float* __restrict__ Wv,
    const float* __restrict__ bq, const float* __restrict__ bk,
    const float* __restrict__ bv, int DIN)
{
    __shared__ float Ash[16][130];           // [k][m], stride 130: conflict-free + 8B aligned
    __shared__ float Wsh[16][128];           // [k][n]
    __shared__ unsigned char sbyte[128][128];

    const int tid = threadIdx.x;
    const int tx = tid & 15, ty = tid >> 4;

    int idx = blockIdx.x;
    int which, m0, n0, K;
    const float *A, *W, *bias;
    if (idx < 512) {
        which = 1 + (idx & 1);
        int s = idx >> 1;
        m0 = (s >> 2) << 7; n0 = (s & 3) << 7; K = DD;
    } else {
        which = 0;
        int s = idx - 512;
        m0 = (s >> 2) << 7; n0 = (s & 3) << 7; K = DIN;
    }
    A    = (which == 0) ? Aq : (which == 1) ? Ak : Av;
    W    = (which == 0) ? Wq : (which == 1) ? Wk : Wv;
    bias = (which == 0) ? bq : (which == 1) ? bk : bv;

    unsigned long long acc[8][4];
#pragma unroll
    for (int i = 0; i < 8; i++)
#pragma unroll
        for (int p = 0; p < 4; p++) acc[i][p] = 0ull;

    const int amm = tid >> 1, akoff = (tid & 1) * 8;
    const int wkk = tid >> 4, wnoff = (tid & 15) * 8;

    for (int k0 = 0; k0 < K; k0 += 16) {
        // A tile -> Ash[k][m]
        if (K == DD) {
            const float4* ap = (const float4*)(A + (size_t)(m0 + amm) * DD + k0 + akoff);
            float4 v0 = ap[0], v1 = ap[1];
            Ash[akoff + 0][amm] = v0.x; Ash[akoff + 1][amm] = v0.y;
            Ash[akoff + 2][amm] = v0.z; Ash[akoff + 3][amm] = v0.w;
            Ash[akoff + 4][amm] = v1.x; Ash[akoff + 5][amm] = v1.y;
            Ash[akoff + 6][amm] = v1.z; Ash[akoff + 7][amm] = v1.w;
        } else {
#pragma unroll
            for (int j = 0; j < 8; j++) {
                int kk = k0 + akoff + j;
                Ash[akoff + j][amm] = (kk < K) ? A[(size_t)(m0 + amm) * K + kk] : 0.f;
            }
        }
        // W tile -> Wsh[k][n]
        if (k0 + wkk < K) {
            const float4* wp = (const float4*)(W + (size_t)(k0 + wkk) * DD + n0 + wnoff);
            float4 w0 = wp[0], w1 = wp[1];
            *(float4*)&Wsh[wkk][wnoff] = w0;
            *(float4*)&Wsh[wkk][wnoff + 4] = w1;
        } else {
            float4 z = {0.f, 0.f, 0.f, 0.f};
            *(float4*)&Wsh[wkk][wnoff] = z;
            *(float4*)&Wsh[wkk][wnoff + 4] = z;
        }
        __syncthreads();
#pragma unroll
        for (int kk = 0; kk < 16; ++kk) {
            unsigned long long av[8];
#pragma unroll
            for (int i = 0; i < 4; i++) {
                unsigned long long au = *(const unsigned long long*)&Ash[kk][ty * 2 + 32 * i];
                float lo, hi; unpk2(au, lo, hi);
                av[2 * i]     = pk2(lo, lo);
                av[2 * i + 1] = pk2(hi, hi);
            }
            unsigned long long wv[4];
#pragma unroll
            for (int p = 0; p < 4; p++)
                wv[p] = *(const unsigned long long*)&Wsh[kk][tx * 2 + 32 * p];
#pragma unroll
            for (int mi = 0; mi < 8; mi++)
#pragma unroll
                for (int p = 0; p < 4; p++) fma2(acc[mi][p], av[mi], wv[p]);
        }
        __syncthreads();
    }

    // spike -> bytes in smem
#pragma unroll
    for (int p = 0; p < 4; p++) {
        float2 bl = *(const float2*)&bias[n0 + tx * 2 + 32 * p];
#pragma unroll
        for (int mi = 0; mi < 8; mi++) {
            float lo, hi; unpk2(acc[mi][p], lo, hi);
            int mloc = ty * 2 + 32 * (mi >> 1) + (mi & 1);
            uchar2 r;
            r.x = (lo + bl.x >= 1.0f) ? 1 : 0;
            r.y = (hi + bl.y >= 1.0f) ? 1 : 0;
            *(uchar2*)&sbyte[mloc][tx * 2 + 32 * p] = r;
        }
    }
    __syncthreads();

    // repack 64 bytes -> one uint64 per (row, head-half)
    {
        int row = tid >> 1, hf = tid & 1;
        unsigned long long bits = 0ull;
#pragma unroll
        for (int q = 0; q < 8; q++) {
            unsigned long long u = *(const unsigned long long*)&sbyte[row][hf * 64 + 8 * q];
#pragma unroll
            for (int j = 0; j < 8; j++)
                bits |= ((u >> (8 * j)) & 1ull) << (8 * q + j);
        }
        int m = m0 + row;
        int b = m >> 11, t = m & 2047;
        int head = (n0 >> 6) + hf;
        unsigned long long* dst = (which == 0) ? g_qb : (which == 1) ? g_kb : g_vb;
        dst[(size_t)((b << 3) + head) * TT + t] = bits;
    }
}

// ---------------- v bit transpose ----------------
__global__ void vtrans_kernel()
{
    int bx = blockIdx.x;
    int bh = bx >> 5, w = bx & 31;
    int tid = threadIdx.x;
    int lane = tid & 31, warp = tid >> 5;
    __shared__ unsigned sh[64][2];
    unsigned long long r = g_vb[(size_t)bh * TT + w * 64 + tid];
#pragma unroll 8
    for (int d = 0; d < 64; d++) {
        unsigned b = __ballot_sync(0xffffffffu, (unsigned)((r >> d) & 1ull));
        if (lane == 0) sh[d][warp] = b;
    }
    __syncthreads();
    g_vT[(size_t)(bh * 64 + tid) * 32 + w] =
        (unsigned long long)sh[tid][0] | ((unsigned long long)sh[tid][1] << 32);
}

// =====================================================================
// Attention: QK via popcount -> s8 cnt tile in smem -> PV via IMMA
// mma.sync.m16n8k32.s8 (exact: cnt<=64, v in {0,1}).
// 128 threads = 4 warps, each warp owns 16 q-rows of the 64-row tile.
// =====================================================================
__global__ __launch_bounds__(128) void attn_kernel(const float* __restrict__ scale_p)
{
    const int tid = threadIdx.x;
    const int lane = tid & 31;
    const int warpid = tid >> 5;
    const int g = lane >> 2, tg = lane & 3;
    const int rowA = warpid * 16 + g;

    int bx = blockIdx.x;
    int bh = bx & 31;
    int tq = 31 - (bx >> 5);          // big tiles first

    __shared__ unsigned long long qsh[64];
    __shared__ unsigned long long ksh[64];
    __shared__ unsigned char csh[64 * 68];   // cnt s8 tile (stride 68); reused for x bytes

    const float scale = *scale_p;
    const size_t base = (size_t)bh * TT;

    if (tid < 64) qsh[tid] = g_qb[base + (size_t)tq * 64 + tid];

    int acc[8][4];
#pragma unroll
    for (int nt = 0; nt < 8; nt++)
#pragma unroll
        for (int r = 0; r < 4; r++) acc[nt][r] = 0;

    const int tQ = tid >> 1;          // q-row 0..63 for popcount phase
    const int khalf = tid & 1;        // k-col half

    for (int w = 0; w <= tq; ++w) {
        __syncthreads();              // prev PV done: csh & ksh free
        if (tid < 64) ksh[tid] = g_kb[base + (size_t)w * 64 + tid];
        unsigned long long vt[8];
#pragma unroll
        for (int nt = 0; nt < 8; ++nt)
            vt[nt] = g_vT[((size_t)bh * 64 + nt * 8 + g) * 32 + w];
        __syncthreads();              // ksh ready

        // ---- QK popcount -> s8 tile ----
        {
            unsigned long long q = qsh[tQ];
            const bool diag = (w == tq);
#pragma unroll 2
            for (int k4 = 0; k4 < 32; k4 += 4) {
                unsigned pack = 0;
#pragma unroll
                for (int j = 0; j < 4; ++j) {
                    int kc = khalf * 32 + k4 + j;
                    int c = __popcll(q & ksh[kc]);
                    if (diag && kc > tQ) c = 0;       // causal: keep k <= q
                    pack |= (unsigned)c << (8 * j);
                }
                *(unsigned*)&csh[tQ * 68 + khalf * 32 + k4] = pack;
            }
        }
        __syncthreads();              // cnt ready

        // ---- PV: 16 IMMAs per warp ----
#pragma unroll
        for (int s = 0; s < 2; ++s) {
            unsigned a0 = *(const unsigned*)&csh[rowA * 68 + s * 32 + tg * 4];
            unsigned a1 = *(const unsigned*)&csh[(rowA + 8) * 68 + s * 32 + tg * 4];
            unsigned a2 = *(const unsigned*)&csh[rowA * 68 + s * 32 + 16 + tg * 4];
            unsigned a3 = *(const unsigned*)&csh[(rowA + 8) * 68 + s * 32 + 16 + tg * 4];
#pragma unroll
            for (int nt = 0; nt < 8; ++nt) {
                unsigned b0 = expand4((unsigned)(vt[nt] >> (s * 32 + tg * 4)) & 0xFu);
                unsigned b1 = expand4((unsigned)(vt[nt] >> (s * 32 + 16 + tg * 4)) & 0xFu);
                mma_s8(acc[nt], a0, a1, a2, a3, b0, b1);
            }
        }
    }

    // ---- spike + transpose (to [d][t]) via smem, then scrambled store ----
    __syncthreads();                  // csh free for reuse
#pragma unroll
    for (int nt = 0; nt < 8; ++nt) {
        int d0 = nt * 8 + tg * 2;
        csh[d0 * 68 + rowA]           = ((float)acc[nt][0] * scale >= 1.0f) ? 1 : 0;
        csh[(d0 + 1) * 68 + rowA]     = ((float)acc[nt][1] * scale >= 1.0f) ? 1 : 0;
        csh[d0 * 68 + rowA + 8]       = ((float)acc[nt][2] * scale >= 1.0f) ? 1 : 0;
        csh[(d0 + 1) * 68 + rowA + 8] = ((float)acc[nt][3] * scale >= 1.0f) ? 1 : 0;
    }
    __syncthreads();
    {
        int d = tid >> 1, hf = tid & 1;
        size_t b = (size_t)(bh >> 3), h = (size_t)(bh & 7);
        size_t off = (b << 20) + (h << 17) + ((size_t)d << 11)
                   + (size_t)tq * 64 + (size_t)hf * 32;
#pragma unroll
        for (int q4 = 0; q4 < 32; q4 += 4) {
            unsigned v = *(const unsigned*)&csh[d * 68 + hf * 32 + q4];
            *(unsigned*)(g_xs + off + q4) = v;
        }
    }
}

// =====================================================================
// Output projection (binary A from g_xs), same conflict-free GEMM body.
// =====================================================================
__global__ __launch_bounds__(256, 2) void out_proj_kernel(
    const float* __restrict__ W, const float* __restrict__ bias,
    float* __restrict__ out)
{
    __shared__ float Ash[16][130];
    __shared__ float Wsh[16][128];

    const int tid = threadIdx.x;
    const int tx = tid & 15, ty = tid >> 4;
    const int m0 = blockIdx.y * 128, n0 = blockIdx.x * 128;

    unsigned long long acc[8][4];
#pragma unroll
    for (int i = 0; i < 8; i++)
#pragma unroll
        for (int p = 0; p < 4; p++) acc[i][p] = 0ull;

    const int amm = tid >> 1, akoff = (tid & 1) * 8;
    const int wkk = tid >> 4, wnoff = (tid & 15) * 8;

    for (int k0 = 0; k0 < DD; k0 += 16) {
        unsigned long long xu =
            *(const unsigned long long*)(g_xs + (size_t)(m0 + amm) * DD + k0 + akoff);
#pragma unroll
        for (int j = 0; j < 8; j++)
            Ash[akoff + j][amm] = (float)(int)((xu >> (8 * j)) & 1ull);
        {
            const float4* wp = (const float4*)(W + (size_t)(k0 + wkk) * DD + n0 + wnoff);
            float4 w0 = wp[0], w1 = wp[1];
            *(float4*)&Wsh[wkk][wnoff] = w0;
            *(float4*)&Wsh[wkk][wnoff + 4] = w1;
        }
        __syncthreads();
#pragma unroll
        for (int kk = 0; kk < 16; ++kk) {
            unsigned long long av[8];
#pragma unroll
            for (int i = 0; i < 4; i++) {
                unsigned long long au = *(const unsigned long long*)&Ash[kk][ty * 2 + 32 * i];
                float lo, hi; unpk2(au, lo, hi);
                av[2 * i]     = pk2(lo, lo);
                av[2 * i + 1] = pk2(hi, hi);
            }
            unsigned long long wv[4];
#pragma unroll
            for (int p = 0; p < 4; p++)
                wv[p] = *(const unsigned long long*)&Wsh[kk][tx * 2 + 32 * p];
#pragma unroll
            for (int mi = 0; mi < 8; mi++)
#pragma unroll
                for (int p = 0; p < 4; p++) fma2(acc[mi][p], av[mi], wv[p]);
        }
        __syncthreads();
    }

#pragma unroll
    for (int p = 0; p < 4; p++) {
        float2 bl = *(const float2*)&bias[n0 + tx * 2 + 32 * p];
#pragma unroll
        for (int mi = 0; mi < 8; mi++) {
            float lo, hi; unpk2(acc[mi][p], lo, hi);
            float2 r;
            r.x = (lo + bl.x >= 1.0f) ? 1.0f : 0.0f;
            r.y = (hi + bl.y >= 1.0f) ? 1.0f : 0.0f;
            int m = m0 + ty * 2 + 32 * (mi >> 1) + (mi & 1);
            *(float2*)&out[(size_t)m * DD + n0 + tx * 2 + 32 * p] = r;
        }
    }
}

// ---------------- launch ----------------
extern "C" void kernel_launch(void* const* d_in, const int* in_sizes, int n_in,
                              void* d_out, int out_size)
{
    const float* query = (const float*)d_in[0];
    const float* key   = (const float*)d_in[1];
    const float* value = (const float*)d_in[2];
    const float* scale = (const float*)d_in[3];
    const float* Wq = (const float*)d_in[4];  const float* bq = (const float*)d_in[5];
    const float* Wk = (const float*)d_in[6];  const float* bk = (const float*)d_in[7];
    const float* Wv = (const float*)d_in[8];  const float* bv = (const float*)d_in[9];
    const float* Wo = (const float*)d_in[10]; const float* bo = (const float*)d_in[11];
    float* out = (float*)d_out;

    const int DIN = in_sizes[0] / MROWS;   // 100

    qkv_proj_kernel<<<768, 256>>>(query, key, value, Wq, Wk, Wv, bq, bk, bv, DIN);
    vtrans_kernel<<<BHN * (TT / 64), 64>>>();
    attn_kernel<<<BHN * (TT / 64), 128>>>(scale);
    out_proj_kernel<<<dim3(4, 64), 256>>>(Wo, bo, out);
}